// round 10
// baseline (speedup 1.0000x reference)
#include <cuda_runtime.h>

// Problem constants
#define TT     25
#define FF     14
#define HH     24
#define KK     38     // FF + HH fused input row [x(14) | h(24)]
#define NSTEPS 13     // fwd needs t=0..12, bwd needs t=24..12
#define BTOT   65536
#define BLK    64
#define NCLS   4
#define VS     41     // v-row stride (odd -> conflict-free LDS.32)

typedef unsigned long long u64;

// ---- packed f32x2 helpers (Blackwell) ----
__device__ __forceinline__ u64 pack2(float lo, float hi) {
    u64 r; asm("mov.b64 %0, {%1, %2};" : "=l"(r) : "f"(lo), "f"(hi)); return r;
}
__device__ __forceinline__ u64 dup2(float v) {
    u64 r; asm("mov.b64 %0, {%1, %1};" : "=l"(r) : "f"(v)); return r;
}
__device__ __forceinline__ void unpack2(u64 v, float& lo, float& hi) {
    asm("mov.b64 {%0, %1}, %2;" : "=f"(lo), "=f"(hi) : "l"(v));
}
__device__ __forceinline__ void ffma2(u64& d, u64 a, u64 b) {
    asm("fma.rn.f32x2 %0, %1, %2, %0;" : "+l"(d) : "l"(a), "l"(b));
}

// ---- fast, accurate activations (EX2/RCP: ~2 ulp) ----
__device__ __forceinline__ float ex2f_(float x) {
    float y; asm("ex2.approx.f32 %0, %1;" : "=f"(y) : "f"(x)); return y;
}
__device__ __forceinline__ float rcpf_(float x) {
    float y; asm("rcp.approx.f32 %0, %1;" : "=f"(y) : "f"(x)); return y;
}
__device__ __forceinline__ float sigf_(float x) {
    return rcpf_(1.0f + ex2f_(-1.4426950408889634f * x));
}
__device__ __forceinline__ float tanhf_(float x) {
    x = fminf(fmaxf(x, -30.0f), 30.0f);
    float a = ex2f_(2.8853900817779268f * x);
    return (a - 1.0f) * rcpf_(a + 1.0f);
}

__global__ __launch_bounds__(256)
void init_out_kernel(const float* __restrict__ head_b, float* __restrict__ out)
{
    const int b = blockIdx.x * blockDim.x + threadIdx.x;
    ((float4*)out)[b] = make_float4(head_b[0], head_b[1], head_b[2], head_b[3]);
}

__global__ __launch_bounds__(BLK, 5)
void lstm_kernel(const float* __restrict__ x,
                 const float* __restrict__ wih_f, const float* __restrict__ whh_f,
                 const float* __restrict__ bih_f, const float* __restrict__ bhh_f,
                 const float* __restrict__ wih_b, const float* __restrict__ whh_b,
                 const float* __restrict__ bih_b, const float* __restrict__ bhh_b,
                 const float* __restrict__ head_w, float* __restrict__ out)
{
    __shared__ ulonglong2 s_w[HH * KK];     // 14592 B  {(wi,wf),(wg,wo)} per (j,k)
    __shared__ u64 s_bif[HH];               //   192 B
    __shared__ u64 s_bgo[HH];               //   192 B
    __shared__ float s_hw[NCLS * HH];       //   384 B
    __shared__ float s_v[2 * BLK * VS];     // 20992 B  per-(elem,thread) [x|h] rows

    const int dir = blockIdx.x & 1;
    const float* wih = dir ? wih_b : wih_f;
    const float* whh = dir ? whh_b : whh_f;
    const float* bih = dir ? bih_b : bih_f;
    const float* bhh = dir ? bhh_b : bhh_f;

    for (int i = threadIdx.x; i < HH * KK; i += BLK) {
        int j = i / KK, k = i % KK;
        float wi, wf, wg, wo;
        if (k < FF) {
            wi = wih[j * FF + k];
            wf = wih[(j + HH) * FF + k];
            wg = wih[(j + 2 * HH) * FF + k];
            wo = wih[(j + 3 * HH) * FF + k];
        } else {
            int kk = k - FF;
            wi = whh[j * HH + kk];
            wf = whh[(j + HH) * HH + kk];
            wg = whh[(j + 2 * HH) * HH + kk];
            wo = whh[(j + 3 * HH) * HH + kk];
        }
        ulonglong2 w; w.x = pack2(wi, wf); w.y = pack2(wg, wo);
        s_w[i] = w;
    }
    if (threadIdx.x < HH) {
        int j = threadIdx.x;
        s_bif[j] = pack2(bih[j] + bhh[j],                   bih[j + HH] + bhh[j + HH]);
        s_bgo[j] = pack2(bih[j + 2 * HH] + bhh[j + 2 * HH], bih[j + 3 * HH] + bhh[j + 3 * HH]);
    }
    for (int i = threadIdx.x; i < NCLS * HH; i += BLK) {
        int m = i / HH, j = i % HH;
        s_hw[m * HH + j] = head_w[m * (2 * HH) + dir * HH + j];
    }
    __syncthreads();

    // Two batch elements per thread
    const int b0 = (blockIdx.x >> 1) * (2 * BLK) + threadIdx.x;
    const int b1 = b0 + BLK;

    float* r0 = &s_v[threadIdx.x * VS];
    float* r1 = &s_v[(BLK + threadIdx.x) * VS];

    float c0[HH], c1[HH], hn0[HH], hn1[HH];   // static-indexed -> registers
    #pragma unroll
    for (int j = 0; j < HH; ++j) {
        c0[j] = 0.f; c1[j] = 0.f; hn0[j] = 0.f; hn1[j] = 0.f;
        r0[FF + j] = 0.f; r1[FF + j] = 0.f;   // h(t=-1) = 0
    }

    const float* xb0 = x + (size_t)b0 * (TT * FF);
    const float* xb1 = x + (size_t)b1 * (TT * FF);
    const int t0 = dir ? (TT - 1) : 0;
    const int dt = dir ? -1 : 1;

    for (int s = 0; s < NSTEPS; ++s) {
        const int toff = (t0 + dt * s) * FF;
        #pragma unroll
        for (int k = 0; k < FF / 2; ++k) {
            float2 v0 = __ldg((const float2*)(xb0 + toff) + k);
            float2 v1 = __ldg((const float2*)(xb1 + toff) + k);
            r0[2 * k] = v0.x; r0[2 * k + 1] = v0.y;
            r1[2 * k] = v1.x; r1[2 * k + 1] = v1.y;
        }

        #pragma unroll
        for (int half = 0; half < 2; ++half) {
            const int j0 = half * 12;
            u64 aif0[12], ago0[12], aif1[12], ago1[12];
            #pragma unroll
            for (int jj = 0; jj < 12; ++jj) {
                aif0[jj] = s_bif[j0 + jj];
                ago0[jj] = s_bgo[j0 + jj];
                aif1[jj] = aif0[jj];
                ago1[jj] = ago0[jj];
            }
            #pragma unroll 2
            for (int k = 0; k < KK; ++k) {
                u64 d0 = dup2(r0[k]);          // one LDS.32 + dup per elem per k
                u64 d1 = dup2(r1[k]);
                #pragma unroll
                for (int jj = 0; jj < 12; ++jj) {
                    ulonglong2 w = s_w[(j0 + jj) * KK + k];   // broadcast LDS.128
                    ffma2(aif0[jj], d0, w.x); ffma2(ago0[jj], d0, w.y);
                    ffma2(aif1[jj], d1, w.x); ffma2(ago1[jj], d1, w.y);
                }
            }
            #pragma unroll
            for (int jj = 0; jj < 12; ++jj) {
                const int j = j0 + jj;
                {
                    float ai, af, ag, ao;
                    unpack2(aif0[jj], ai, af); unpack2(ago0[jj], ag, ao);
                    float ii = sigf_(ai), ff = sigf_(af), oo = sigf_(ao), gg = tanhf_(ag);
                    float cn = ff * c0[j] + ii * gg;
                    c0[j] = cn; hn0[j] = oo * tanhf_(cn);
                }
                {
                    float ai, af, ag, ao;
                    unpack2(aif1[jj], ai, af); unpack2(ago1[jj], ag, ao);
                    float ii = sigf_(ai), ff = sigf_(af), oo = sigf_(ao), gg = tanhf_(ag);
                    float cn = ff * c1[j] + ii * gg;
                    c1[j] = cn; hn1[j] = oo * tanhf_(cn);
                }
            }
        }
        // publish h(t) for next step (private rows, no sync needed)
        #pragma unroll
        for (int j = 0; j < HH; ++j) { r0[FF + j] = hn0[j]; r1[FF + j] = hn1[j]; }
    }

    // Fused head: partial logits for this direction, accumulated atomically.
    float p00 = 0.f, p01 = 0.f, p02 = 0.f, p03 = 0.f;
    float p10 = 0.f, p11 = 0.f, p12 = 0.f, p13 = 0.f;
    #pragma unroll
    for (int j = 0; j < HH; ++j) {
        float w0 = s_hw[j], w1 = s_hw[HH + j], w2 = s_hw[2 * HH + j], w3 = s_hw[3 * HH + j];
        p00 += hn0[j] * w0; p01 += hn0[j] * w1; p02 += hn0[j] * w2; p03 += hn0[j] * w3;
        p10 += hn1[j] * w0; p11 += hn1[j] * w1; p12 += hn1[j] * w2; p13 += hn1[j] * w3;
    }
    float* ob0 = out + (size_t)b0 * NCLS;
    atomicAdd(ob0 + 0, p00); atomicAdd(ob0 + 1, p01);
    atomicAdd(ob0 + 2, p02); atomicAdd(ob0 + 3, p03);
    float* ob1 = out + (size_t)b1 * NCLS;
    atomicAdd(ob1 + 0, p10); atomicAdd(ob1 + 1, p11);
    atomicAdd(ob1 + 2, p12); atomicAdd(ob1 + 3, p13);
}

extern "C" void kernel_launch(void* const* d_in, const int* in_sizes, int n_in,
                              void* d_out, int out_size)
{
    const float* x      = (const float*)d_in[0];
    const float* wih_f  = (const float*)d_in[1];
    const float* whh_f  = (const float*)d_in[2];
    const float* bih_f  = (const float*)d_in[3];
    const float* bhh_f  = (const float*)d_in[4];
    const float* wih_b  = (const float*)d_in[5];
    const float* whh_b  = (const float*)d_in[6];
    const float* bih_b  = (const float*)d_in[7];
    const float* bhh_b  = (const float*)d_in[8];
    const float* head_w = (const float*)d_in[9];
    const float* head_b = (const float*)d_in[10];
    float* out = (float*)d_out;

    init_out_kernel<<<BTOT / 256, 256>>>(head_b, out);
    lstm_kernel<<<(BTOT / (2 * BLK)) * 2, BLK>>>(x, wih_f, whh_f, bih_f, bhh_f,
                                                 wih_b, whh_b, bih_b, bhh_b,
                                                 head_w, out);
}

// round 11
// speedup vs baseline: 1.6439x; 1.6439x over previous
#include <cuda_runtime.h>

// Problem constants
#define TT     25
#define FF     14
#define HH     24
#define KK     38     // FF + HH fused weight row
#define NSTEPS 13     // fwd needs t=0..12, bwd needs t=24..12
#define BTOT   65536
#define BLK    128
#define EPB    128    // elems per CTA
#define JH     12     // j's per half-warp-group
#define NCLS   4

typedef unsigned long long u64;

__device__ __forceinline__ u64 pack2(float lo, float hi) {
    u64 r; asm("mov.b64 %0, {%1, %2};" : "=l"(r) : "f"(lo), "f"(hi)); return r;
}
__device__ __forceinline__ u64 dup2(float v) {
    u64 r; asm("mov.b64 %0, {%1, %1};" : "=l"(r) : "f"(v)); return r;
}
__device__ __forceinline__ void unpack2(u64 v, float& lo, float& hi) {
    asm("mov.b64 {%0, %1}, %2;" : "=f"(lo), "=f"(hi) : "l"(v));
}
__device__ __forceinline__ void ffma2(u64& d, u64 a, u64 b) {
    asm("fma.rn.f32x2 %0, %1, %2, %0;" : "+l"(d) : "l"(a), "l"(b));
}

// ---- exact-enough activations (EX2/RCP ~2ulp) ----
__device__ __forceinline__ float ex2f_(float x) {
    float y; asm("ex2.approx.f32 %0, %1;" : "=f"(y) : "f"(x)); return y;
}
__device__ __forceinline__ float rcpf_(float x) {
    float y; asm("rcp.approx.f32 %0, %1;" : "=f"(y) : "f"(x)); return y;
}
__device__ __forceinline__ float sigf_(float x) {
    return rcpf_(1.0f + ex2f_(-1.4426950408889634f * x));
}
// tanh(x) = 2*sigmoid(2x) - 1 ; saturates correctly at +-inf, no clamp needed
__device__ __forceinline__ float tanhf_(float x) {
    float a = ex2f_(-2.8853900817779268f * x);
    float r = rcpf_(1.0f + a);
    return fmaf(2.0f, r, -1.0f);
}

__global__ __launch_bounds__(256)
void init_out_kernel(const float* __restrict__ head_b, float* __restrict__ out)
{
    const int b = blockIdx.x * blockDim.x + threadIdx.x;
    ((float4*)out)[b] = make_float4(head_b[0], head_b[1], head_b[2], head_b[3]);
}

__global__ __launch_bounds__(BLK, 4)
void lstm_kernel(const float* __restrict__ x,
                 const float* __restrict__ wih_f, const float* __restrict__ whh_f,
                 const float* __restrict__ bih_f, const float* __restrict__ bhh_f,
                 const float* __restrict__ wih_b, const float* __restrict__ whh_b,
                 const float* __restrict__ bih_b, const float* __restrict__ bhh_b,
                 const float* __restrict__ head_w, float* __restrict__ out)
{
    __shared__ ulonglong2 s_w[HH * KK];       // 14592 B {(wi,wf),(wg,wo)}
    __shared__ u64 s_bif[HH];                 //   192 B
    __shared__ u64 s_bgo[HH];                 //   192 B
    __shared__ float s_hw[NCLS * HH];         //   384 B
    __shared__ float s_c[BLK * 25];           // 12800 B  c: [thread][jj(12)+elem*12]
    __shared__ float s_h[2 * EPB * 25];       // 25600 B  h ping-pong: [buf][elem][j]

    const int tid  = threadIdx.x;
    const int e    = tid & 63;
    const int half = tid >> 6;
    const int j0   = half * JH;

    const int dir = blockIdx.x & 1;
    const float* wih = dir ? wih_b : wih_f;
    const float* whh = dir ? whh_b : whh_f;
    const float* bih = dir ? bih_b : bih_f;
    const float* bhh = dir ? bhh_b : bhh_f;

    for (int i = tid; i < HH * KK; i += BLK) {
        int j = i / KK, k = i % KK;
        float wi, wf, wg, wo;
        if (k < FF) {
            wi = wih[j * FF + k];
            wf = wih[(j + HH) * FF + k];
            wg = wih[(j + 2 * HH) * FF + k];
            wo = wih[(j + 3 * HH) * FF + k];
        } else {
            int kk = k - FF;
            wi = whh[j * HH + kk];
            wf = whh[(j + HH) * HH + kk];
            wg = whh[(j + 2 * HH) * HH + kk];
            wo = whh[(j + 3 * HH) * HH + kk];
        }
        ulonglong2 w; w.x = pack2(wi, wf); w.y = pack2(wg, wo);
        s_w[i] = w;
    }
    if (tid < HH) {
        int j = tid;
        s_bif[j] = pack2(bih[j] + bhh[j],                   bih[j + HH] + bhh[j + HH]);
        s_bgo[j] = pack2(bih[j + 2 * HH] + bhh[j + 2 * HH], bih[j + 3 * HH] + bhh[j + 3 * HH]);
    }
    if (tid < NCLS * HH) {
        int m = tid / HH, j = tid % HH;
        s_hw[m * HH + j] = head_w[m * (2 * HH) + dir * HH + j];
    }

    // zero h ping buffer (each thread zeros its own write-cols) and c
    float* ct = &s_c[tid * 25];
    #pragma unroll
    for (int jj = 0; jj < JH; ++jj) {
        s_h[e * 25 + j0 + jj]        = 0.f;
        s_h[(64 + e) * 25 + j0 + jj] = 0.f;
        ct[jj] = 0.f; ct[JH + jj] = 0.f;
    }
    __syncthreads();

    const int base = (blockIdx.x >> 1) * EPB;
    const int b0 = base + e;
    const int b1 = base + 64 + e;
    const float* xb0 = x + (size_t)b0 * (TT * FF);
    const float* xb1 = x + (size_t)b1 * (TT * FF);
    const int t0 = dir ? (TT - 1) : 0;
    const int dt = dir ? -1 : 1;

    int ping = 0;
    for (int s = 0; s < NSTEPS; ++s) {
        const int toff = (t0 + dt * s) * FF;
        float xv0[FF], xv1[FF];
        #pragma unroll
        for (int k = 0; k < FF / 2; ++k) {
            float2 v0 = __ldg((const float2*)(xb0 + toff) + k);
            float2 v1 = __ldg((const float2*)(xb1 + toff) + k);
            xv0[2 * k] = v0.x; xv0[2 * k + 1] = v0.y;
            xv1[2 * k] = v1.x; xv1[2 * k + 1] = v1.y;
        }
        // preload full h of both elems into registers (static-indexed)
        float hr0[HH], hr1[HH];
        const float* hp0 = &s_h[ping * (EPB * 25) + e * 25];
        const float* hp1 = &s_h[ping * (EPB * 25) + (64 + e) * 25];
        #pragma unroll
        for (int k = 0; k < HH; ++k) { hr0[k] = hp0[k]; hr1[k] = hp1[k]; }

        float* wr0 = &s_h[(ping ^ 1) * (EPB * 25) + e * 25];
        float* wr1 = &s_h[(ping ^ 1) * (EPB * 25) + (64 + e) * 25];

        #pragma unroll 1
        for (int jj = 0; jj < JH; ++jj) {
            const int j = j0 + jj;
            u64 aif0 = s_bif[j], ago0 = s_bgo[j];
            u64 aif1 = aif0,     ago1 = ago0;
            const ulonglong2* wp = &s_w[j * KK];
            #pragma unroll
            for (int k = 0; k < FF; ++k) {
                ulonglong2 w = wp[k];                    // broadcast LDS.128
                u64 d0 = dup2(xv0[k]);
                u64 d1 = dup2(xv1[k]);
                ffma2(aif0, d0, w.x); ffma2(ago0, d0, w.y);
                ffma2(aif1, d1, w.x); ffma2(ago1, d1, w.y);
            }
            #pragma unroll
            for (int k = 0; k < HH; ++k) {
                ulonglong2 w = wp[FF + k];
                u64 d0 = dup2(hr0[k]);
                u64 d1 = dup2(hr1[k]);
                ffma2(aif0, d0, w.x); ffma2(ago0, d0, w.y);
                ffma2(aif1, d1, w.x); ffma2(ago1, d1, w.y);
            }
            {
                float ai, af, ag, ao;
                unpack2(aif0, ai, af); unpack2(ago0, ag, ao);
                float ii = sigf_(ai), ff = sigf_(af), oo = sigf_(ao), gg = tanhf_(ag);
                float cn = ff * ct[jj] + ii * gg;
                ct[jj] = cn;
                wr0[j] = oo * tanhf_(cn);
            }
            {
                float ai, af, ag, ao;
                unpack2(aif1, ai, af); unpack2(ago1, ag, ao);
                float ii = sigf_(ai), ff = sigf_(af), oo = sigf_(ao), gg = tanhf_(ag);
                float cn = ff * ct[JH + jj] + ii * gg;
                ct[JH + jj] = cn;
                wr1[j] = oo * tanhf_(cn);
            }
        }
        __syncthreads();     // publish h(t) to the other half's warps
        ping ^= 1;
    }

    // Head: thread tid handles elem row tid (full h now in s_h[ping])
    const float* hf = &s_h[ping * (EPB * 25) + tid * 25];
    float p0 = 0.f, p1 = 0.f, p2 = 0.f, p3 = 0.f;
    #pragma unroll
    for (int j = 0; j < HH; ++j) {
        float v = hf[j];
        p0 += v * s_hw[j];
        p1 += v * s_hw[HH + j];
        p2 += v * s_hw[2 * HH + j];
        p3 += v * s_hw[3 * HH + j];
    }
    float* ob = out + (size_t)(base + tid) * NCLS;
    atomicAdd(ob + 0, p0); atomicAdd(ob + 1, p1);
    atomicAdd(ob + 2, p2); atomicAdd(ob + 3, p3);
}

extern "C" void kernel_launch(void* const* d_in, const int* in_sizes, int n_in,
                              void* d_out, int out_size)
{
    const float* x      = (const float*)d_in[0];
    const float* wih_f  = (const float*)d_in[1];
    const float* whh_f  = (const float*)d_in[2];
    const float* bih_f  = (const float*)d_in[3];
    const float* bhh_f  = (const float*)d_in[4];
    const float* wih_b  = (const float*)d_in[5];
    const float* whh_b  = (const float*)d_in[6];
    const float* bih_b  = (const float*)d_in[7];
    const float* bhh_b  = (const float*)d_in[8];
    const float* head_w = (const float*)d_in[9];
    const float* head_b = (const float*)d_in[10];
    float* out = (float*)d_out;

    init_out_kernel<<<BTOT / 256, 256>>>(head_b, out);
    // 512 elem-tiles x 2 directions; 4 CTAs/SM, 16 warps/SM
    lstm_kernel<<<(BTOT / EPB) * 2, BLK>>>(x, wih_f, whh_f, bih_f, bhh_f,
                                           wih_b, whh_b, bih_b, bhh_b,
                                           head_w, out);
}

// round 12
// speedup vs baseline: 1.7417x; 1.0595x over previous
#include <cuda_runtime.h>

// Problem constants
#define TT     25
#define FF     14
#define HH     24
#define KK     38     // FF + HH fused weight row
#define NSTEPS 13     // fwd needs t=0..12, bwd needs t=24..12
#define BTOT   65536
#define BLK    128
#define EPB    128    // elems per CTA
#define JH     12     // j's per half
#define NCLS   4
#define XS     15     // s_x row stride (odd -> conflict-free)

typedef unsigned long long u64;

__device__ __forceinline__ u64 pack2(float lo, float hi) {
    u64 r; asm("mov.b64 %0, {%1, %2};" : "=l"(r) : "f"(lo), "f"(hi)); return r;
}
__device__ __forceinline__ u64 dup2(float v) {
    u64 r; asm("mov.b64 %0, {%1, %1};" : "=l"(r) : "f"(v)); return r;
}
__device__ __forceinline__ void unpack2(u64 v, float& lo, float& hi) {
    asm("mov.b64 {%0, %1}, %2;" : "=f"(lo), "=f"(hi) : "l"(v));
}
__device__ __forceinline__ void ffma2(u64& d, u64 a, u64 b) {
    asm("fma.rn.f32x2 %0, %1, %2, %0;" : "+l"(d) : "l"(a), "l"(b));
}

__device__ __forceinline__ float ex2f_(float x) {
    float y; asm("ex2.approx.f32 %0, %1;" : "=f"(y) : "f"(x)); return y;
}
__device__ __forceinline__ float rcpf_(float x) {
    float y; asm("rcp.approx.f32 %0, %1;" : "=f"(y) : "f"(x)); return y;
}
__device__ __forceinline__ float sigf_(float x) {
    return rcpf_(1.0f + ex2f_(-1.4426950408889634f * x));
}
// tanh(x) = 2*sigmoid(2x) - 1
__device__ __forceinline__ float tanhf_(float x) {
    float a = ex2f_(-2.8853900817779268f * x);
    float r = rcpf_(1.0f + a);
    return fmaf(2.0f, r, -1.0f);
}

__global__ __launch_bounds__(256)
void init_out_kernel(const float* __restrict__ head_b, float* __restrict__ out)
{
    const int b = blockIdx.x * blockDim.x + threadIdx.x;
    ((float4*)out)[b] = make_float4(head_b[0], head_b[1], head_b[2], head_b[3]);
}

__global__ __launch_bounds__(BLK, 4)
void lstm_kernel(const float* __restrict__ x,
                 const float* __restrict__ wih_f, const float* __restrict__ whh_f,
                 const float* __restrict__ bih_f, const float* __restrict__ bhh_f,
                 const float* __restrict__ wih_b, const float* __restrict__ whh_b,
                 const float* __restrict__ bih_b, const float* __restrict__ bhh_b,
                 const float* __restrict__ head_w, float* __restrict__ out)
{
    __shared__ ulonglong2 s_w[HH * KK];       // 14592 B {(wi,wf),(wg,wo)}
    __shared__ u64 s_bif[HH];                 //   192 B
    __shared__ u64 s_bgo[HH];                 //   192 B
    __shared__ float s_hw[NCLS * HH];         //   384 B
    __shared__ float s_c[BLK * 25];           // 12800 B  c: [thread][jj + elem*12]
    __shared__ float s_h[EPB * 25];           // 12800 B  h single buffer [elem][j]
    __shared__ float s_x[EPB * XS];           //  7680 B  staged x slice [elem][f]

    const int tid  = threadIdx.x;
    const int e    = tid & 63;
    const int half = tid >> 6;
    const int j0   = half * JH;

    const int dir = blockIdx.x & 1;
    const float* wih = dir ? wih_b : wih_f;
    const float* whh = dir ? whh_b : whh_f;
    const float* bih = dir ? bih_b : bih_f;
    const float* bhh = dir ? bhh_b : bhh_f;

    for (int i = tid; i < HH * KK; i += BLK) {
        int j = i / KK, k = i % KK;
        float wi, wf, wg, wo;
        if (k < FF) {
            wi = wih[j * FF + k];
            wf = wih[(j + HH) * FF + k];
            wg = wih[(j + 2 * HH) * FF + k];
            wo = wih[(j + 3 * HH) * FF + k];
        } else {
            int kk = k - FF;
            wi = whh[j * HH + kk];
            wf = whh[(j + HH) * HH + kk];
            wg = whh[(j + 2 * HH) * HH + kk];
            wo = whh[(j + 3 * HH) * HH + kk];
        }
        ulonglong2 w; w.x = pack2(wi, wf); w.y = pack2(wg, wo);
        s_w[i] = w;
    }
    if (tid < HH) {
        int j = tid;
        s_bif[j] = pack2(bih[j] + bhh[j],                   bih[j + HH] + bhh[j + HH]);
        s_bgo[j] = pack2(bih[j + 2 * HH] + bhh[j + 2 * HH], bih[j + 3 * HH] + bhh[j + 3 * HH]);
    }
    if (tid < NCLS * HH) {
        int m = tid / HH, j = tid % HH;
        s_hw[m * HH + j] = head_w[m * (2 * HH) + dir * HH + j];
    }

    const int base = (blockIdx.x >> 1) * EPB;
    const int t0 = dir ? (TT - 1) : 0;
    const int dt = dir ? -1 : 1;

    // zero h buffer (each thread its write-cols) and c; stage x(step 0)
    float* ct = &s_c[tid * 25];
    #pragma unroll
    for (int jj = 0; jj < JH; ++jj) {
        s_h[e * 25 + j0 + jj]        = 0.f;
        s_h[(64 + e) * 25 + j0 + jj] = 0.f;
        ct[jj] = 0.f; ct[JH + jj] = 0.f;
    }
    {
        const int t = t0;
        #pragma unroll
        for (int idx = tid; idx < EPB * (FF / 2); idx += BLK) {
            int ee = idx / 7, f2 = idx - ee * 7;
            float2 v = __ldg((const float2*)(x + (size_t)(base + ee) * (TT * FF) + t * FF) + f2);
            s_x[ee * XS + 2 * f2]     = v.x;
            s_x[ee * XS + 2 * f2 + 1] = v.y;
        }
    }
    __syncthreads();

    for (int s = 0; s < NSTEPS; ++s) {
        // ---- read phase: x and h(s-1) into registers ----
        float xv0[FF], xv1[FF], hr0[HH], hr1[HH];
        const float* xp0 = &s_x[e * XS];
        const float* xp1 = &s_x[(64 + e) * XS];
        const float* hp0 = &s_h[e * 25];
        const float* hp1 = &s_h[(64 + e) * 25];
        #pragma unroll
        for (int k = 0; k < FF; ++k) { xv0[k] = xp0[k]; xv1[k] = xp1[k]; }
        #pragma unroll
        for (int k = 0; k < HH; ++k) { hr0[k] = hp0[k]; hr1[k] = hp1[k]; }
        __syncthreads();            // BAR1: all reads done before overwrites

        float* wr0 = &s_h[e * 25];
        float* wr1 = &s_h[(64 + e) * 25];

        #pragma unroll 1
        for (int jj = 0; jj < JH; ++jj) {
            const int j = j0 + jj;
            u64 aif0 = s_bif[j], ago0 = s_bgo[j];
            u64 aif1 = aif0,     ago1 = ago0;
            const ulonglong2* wp = &s_w[j * KK];
            #pragma unroll
            for (int k = 0; k < FF; ++k) {
                ulonglong2 w = wp[k];                    // broadcast LDS.128
                u64 d0 = dup2(xv0[k]);
                u64 d1 = dup2(xv1[k]);
                ffma2(aif0, d0, w.x); ffma2(ago0, d0, w.y);
                ffma2(aif1, d1, w.x); ffma2(ago1, d1, w.y);
            }
            #pragma unroll
            for (int k = 0; k < HH; ++k) {
                ulonglong2 w = wp[FF + k];
                u64 d0 = dup2(hr0[k]);
                u64 d1 = dup2(hr1[k]);
                ffma2(aif0, d0, w.x); ffma2(ago0, d0, w.y);
                ffma2(aif1, d1, w.x); ffma2(ago1, d1, w.y);
            }
            {
                float ai, af, ag, ao;
                unpack2(aif0, ai, af); unpack2(ago0, ag, ao);
                float ii = sigf_(ai), ff = sigf_(af), oo = sigf_(ao), gg = tanhf_(ag);
                float cn = ff * ct[jj] + ii * gg;
                ct[jj] = cn;
                wr0[j] = oo * tanhf_(cn);
            }
            {
                float ai, af, ag, ao;
                unpack2(aif1, ai, af); unpack2(ago1, ag, ao);
                float ii = sigf_(ai), ff = sigf_(af), oo = sigf_(ao), gg = tanhf_(ag);
                float cn = ff * ct[JH + jj] + ii * gg;
                ct[JH + jj] = cn;
                wr1[j] = oo * tanhf_(cn);
            }
        }

        // stage x for next step (coalesced) while h writes land
        if (s + 1 < NSTEPS) {
            const int t = t0 + dt * (s + 1);
            #pragma unroll
            for (int idx = tid; idx < EPB * (FF / 2); idx += BLK) {
                int ee = idx / 7, f2 = idx - ee * 7;
                float2 v = __ldg((const float2*)(x + (size_t)(base + ee) * (TT * FF) + t * FF) + f2);
                s_x[ee * XS + 2 * f2]     = v.x;
                s_x[ee * XS + 2 * f2 + 1] = v.y;
            }
        }
        __syncthreads();            // BAR2: h(s) + x(s+1) visible
    }

    // Head: thread tid handles elem row tid (full h in s_h)
    const float* hf = &s_h[tid * 25];
    float p0 = 0.f, p1 = 0.f, p2 = 0.f, p3 = 0.f;
    #pragma unroll
    for (int j = 0; j < HH; ++j) {
        float v = hf[j];
        p0 += v * s_hw[j];
        p1 += v * s_hw[HH + j];
        p2 += v * s_hw[2 * HH + j];
        p3 += v * s_hw[3 * HH + j];
    }
    float* ob = out + (size_t)(base + tid) * NCLS;
    atomicAdd(ob + 0, p0); atomicAdd(ob + 1, p1);
    atomicAdd(ob + 2, p2); atomicAdd(ob + 3, p3);
}

extern "C" void kernel_launch(void* const* d_in, const int* in_sizes, int n_in,
                              void* d_out, int out_size)
{
    const float* x      = (const float*)d_in[0];
    const float* wih_f  = (const float*)d_in[1];
    const float* whh_f  = (const float*)d_in[2];
    const float* bih_f  = (const float*)d_in[3];
    const float* bhh_f  = (const float*)d_in[4];
    const float* wih_b  = (const float*)d_in[5];
    const float* whh_b  = (const float*)d_in[6];
    const float* bih_b  = (const float*)d_in[7];
    const float* bhh_b  = (const float*)d_in[8];
    const float* head_w = (const float*)d_in[9];
    const float* head_b = (const float*)d_in[10];
    float* out = (float*)d_out;

    init_out_kernel<<<BTOT / 256, 256>>>(head_b, out);
    lstm_kernel<<<(BTOT / EPB) * 2, BLK>>>(x, wih_f, whh_f, bih_f, bhh_f,
                                           wih_b, whh_b, bih_b, bhh_b,
                                           head_w, out);
}

// round 13
// speedup vs baseline: 1.7717x; 1.0172x over previous
#include <cuda_runtime.h>

// Problem constants
#define TT     25
#define FF     14
#define HH     24
#define KK     38     // FF + HH fused weight row
#define NSTEPS 13     // fwd needs t=0..12, bwd needs t=24..12
#define BTOT   65536
#define BLK    128
#define EPB    128    // elems per CTA
#define JH     12     // j's per half
#define NCLS   4
#define XS     15     // s_x row stride (odd -> conflict-free)

typedef unsigned long long u64;

__device__ __forceinline__ u64 pack2(float lo, float hi) {
    u64 r; asm("mov.b64 %0, {%1, %2};" : "=l"(r) : "f"(lo), "f"(hi)); return r;
}
__device__ __forceinline__ u64 dup2(float v) {
    u64 r; asm("mov.b64 %0, {%1, %1};" : "=l"(r) : "f"(v)); return r;
}
__device__ __forceinline__ void unpack2(u64 v, float& lo, float& hi) {
    asm("mov.b64 {%0, %1}, %2;" : "=f"(lo), "=f"(hi) : "l"(v));
}
__device__ __forceinline__ void ffma2(u64& d, u64 a, u64 b) {
    asm("fma.rn.f32x2 %0, %1, %2, %0;" : "+l"(d) : "l"(a), "l"(b));
}

__device__ __forceinline__ float ex2f_(float x) {
    float y; asm("ex2.approx.f32 %0, %1;" : "=f"(y) : "f"(x)); return y;
}
__device__ __forceinline__ float rcpf_(float x) {
    float y; asm("rcp.approx.f32 %0, %1;" : "=f"(y) : "f"(x)); return y;
}
__device__ __forceinline__ float sigf_(float x) {
    return rcpf_(1.0f + ex2f_(-1.4426950408889634f * x));
}
// tanh(x) = 2*sigmoid(2x) - 1
__device__ __forceinline__ float tanhf_(float x) {
    float a = ex2f_(-2.8853900817779268f * x);
    float r = rcpf_(1.0f + a);
    return fmaf(2.0f, r, -1.0f);
}

__global__ __launch_bounds__(256)
void init_out_kernel(const float* __restrict__ head_b, float* __restrict__ out)
{
    const int b = blockIdx.x * blockDim.x + threadIdx.x;
    ((float4*)out)[b] = make_float4(head_b[0], head_b[1], head_b[2], head_b[3]);
}

__global__ __launch_bounds__(BLK, 4)
void lstm_kernel(const float* __restrict__ x,
                 const float* __restrict__ wih_f, const float* __restrict__ whh_f,
                 const float* __restrict__ bih_f, const float* __restrict__ bhh_f,
                 const float* __restrict__ wih_b, const float* __restrict__ whh_b,
                 const float* __restrict__ bih_b, const float* __restrict__ bhh_b,
                 const float* __restrict__ head_w, float* __restrict__ out)
{
    __shared__ ulonglong2 s_w[HH * KK];       // 14592 B {(wi,wf),(wg,wo)}
    __shared__ u64 s_bif[HH];                 //   192 B
    __shared__ u64 s_bgo[HH];                 //   192 B
    __shared__ float s_hw[NCLS * HH];         //   384 B
    __shared__ float s_c[BLK * 25];           // 12800 B  c: [thread][jj + elem*12]
    __shared__ float s_h[EPB * 25];           // 12800 B  h single buffer [elem][j]
    __shared__ float s_x[EPB * XS];           //  7680 B  staged x slice [elem][f]

    const int tid  = threadIdx.x;
    const int e    = tid & 63;
    const int half = tid >> 6;
    const int j0   = half * JH;

    const int dir = blockIdx.x & 1;
    const float* wih = dir ? wih_b : wih_f;
    const float* whh = dir ? whh_b : whh_f;
    const float* bih = dir ? bih_b : bih_f;
    const float* bhh = dir ? bhh_b : bhh_f;

    for (int i = tid; i < HH * KK; i += BLK) {
        int j = i / KK, k = i % KK;
        float wi, wf, wg, wo;
        if (k < FF) {
            wi = wih[j * FF + k];
            wf = wih[(j + HH) * FF + k];
            wg = wih[(j + 2 * HH) * FF + k];
            wo = wih[(j + 3 * HH) * FF + k];
        } else {
            int kk = k - FF;
            wi = whh[j * HH + kk];
            wf = whh[(j + HH) * HH + kk];
            wg = whh[(j + 2 * HH) * HH + kk];
            wo = whh[(j + 3 * HH) * HH + kk];
        }
        ulonglong2 w; w.x = pack2(wi, wf); w.y = pack2(wg, wo);
        s_w[i] = w;
    }
    if (tid < HH) {
        int j = tid;
        s_bif[j] = pack2(bih[j] + bhh[j],                   bih[j + HH] + bhh[j + HH]);
        s_bgo[j] = pack2(bih[j + 2 * HH] + bhh[j + 2 * HH], bih[j + 3 * HH] + bhh[j + 3 * HH]);
    }
    if (tid < NCLS * HH) {
        int m = tid / HH, j = tid % HH;
        s_hw[m * HH + j] = head_w[m * (2 * HH) + dir * HH + j];
    }

    const int base = (blockIdx.x >> 1) * EPB;
    const int t0 = dir ? (TT - 1) : 0;
    const int dt = dir ? -1 : 1;

    // zero h buffer (each thread its write-cols) and c; stage x(step 0)
    float* ct = &s_c[tid * 25];
    #pragma unroll
    for (int jj = 0; jj < JH; ++jj) {
        s_h[e * 25 + j0 + jj]        = 0.f;
        s_h[(64 + e) * 25 + j0 + jj] = 0.f;
        ct[jj] = 0.f; ct[JH + jj] = 0.f;
    }
    {
        const int t = t0;
        #pragma unroll
        for (int idx = tid; idx < EPB * (FF / 2); idx += BLK) {
            int ee = idx / 7, f2 = idx - ee * 7;
            float2 v = __ldg((const float2*)(x + (size_t)(base + ee) * (TT * FF) + t * FF) + f2);
            s_x[ee * XS + 2 * f2]     = v.x;
            s_x[ee * XS + 2 * f2 + 1] = v.y;
        }
    }
    __syncthreads();

    for (int s = 0; s < NSTEPS; ++s) {
        // ---- read phase: x and h(s-1) into registers ----
        float xv0[FF], xv1[FF], hr0[HH], hr1[HH];
        const float* xp0 = &s_x[e * XS];
        const float* xp1 = &s_x[(64 + e) * XS];
        const float* hp0 = &s_h[e * 25];
        const float* hp1 = &s_h[(64 + e) * 25];
        #pragma unroll
        for (int k = 0; k < FF; ++k) { xv0[k] = xp0[k]; xv1[k] = xp1[k]; }
        #pragma unroll
        for (int k = 0; k < HH; ++k) { hr0[k] = hp0[k]; hr1[k] = hp1[k]; }
        __syncthreads();            // BAR1: all reads done before overwrites

        float* wr0 = &s_h[e * 25];
        float* wr1 = &s_h[(64 + e) * 25];

        #pragma unroll 4
        for (int jj = 0; jj < JH; ++jj) {
            const int j = j0 + jj;
            u64 aif0 = s_bif[j], ago0 = s_bgo[j];
            u64 aif1 = aif0,     ago1 = ago0;
            const ulonglong2* wp = &s_w[j * KK];
            #pragma unroll
            for (int k = 0; k < FF; ++k) {
                ulonglong2 w = wp[k];                    // broadcast LDS.128
                u64 d0 = dup2(xv0[k]);
                u64 d1 = dup2(xv1[k]);
                ffma2(aif0, d0, w.x); ffma2(ago0, d0, w.y);
                ffma2(aif1, d1, w.x); ffma2(ago1, d1, w.y);
            }
            #pragma unroll
            for (int k = 0; k < HH; ++k) {
                ulonglong2 w = wp[FF + k];
                u64 d0 = dup2(hr0[k]);
                u64 d1 = dup2(hr1[k]);
                ffma2(aif0, d0, w.x); ffma2(ago0, d0, w.y);
                ffma2(aif1, d1, w.x); ffma2(ago1, d1, w.y);
            }
            {
                float ai, af, ag, ao;
                unpack2(aif0, ai, af); unpack2(ago0, ag, ao);
                float ii = sigf_(ai), ff = sigf_(af), oo = sigf_(ao), gg = tanhf_(ag);
                float cn = ff * ct[jj] + ii * gg;
                ct[jj] = cn;
                wr0[j] = oo * tanhf_(cn);
            }
            {
                float ai, af, ag, ao;
                unpack2(aif1, ai, af); unpack2(ago1, ag, ao);
                float ii = sigf_(ai), ff = sigf_(af), oo = sigf_(ao), gg = tanhf_(ag);
                float cn = ff * ct[JH + jj] + ii * gg;
                ct[JH + jj] = cn;
                wr1[j] = oo * tanhf_(cn);
            }
        }

        // stage x for next step (coalesced) while h writes land
        if (s + 1 < NSTEPS) {
            const int t = t0 + dt * (s + 1);
            #pragma unroll
            for (int idx = tid; idx < EPB * (FF / 2); idx += BLK) {
                int ee = idx / 7, f2 = idx - ee * 7;
                float2 v = __ldg((const float2*)(x + (size_t)(base + ee) * (TT * FF) + t * FF) + f2);
                s_x[ee * XS + 2 * f2]     = v.x;
                s_x[ee * XS + 2 * f2 + 1] = v.y;
            }
        }
        __syncthreads();            // BAR2: h(s) + x(s+1) visible
    }

    // Head: thread tid handles elem row tid (full h in s_h)
    const float* hf = &s_h[tid * 25];
    float p0 = 0.f, p1 = 0.f, p2 = 0.f, p3 = 0.f;
    #pragma unroll
    for (int j = 0; j < HH; ++j) {
        float v = hf[j];
        p0 += v * s_hw[j];
        p1 += v * s_hw[HH + j];
        p2 += v * s_hw[2 * HH + j];
        p3 += v * s_hw[3 * HH + j];
    }
    float* ob = out + (size_t)(base + tid) * NCLS;
    atomicAdd(ob + 0, p0); atomicAdd(ob + 1, p1);
    atomicAdd(ob + 2, p2); atomicAdd(ob + 3, p3);
}

extern "C" void kernel_launch(void* const* d_in, const int* in_sizes, int n_in,
                              void* d_out, int out_size)
{
    const float* x      = (const float*)d_in[0];
    const float* wih_f  = (const float*)d_in[1];
    const float* whh_f  = (const float*)d_in[2];
    const float* bih_f  = (const float*)d_in[3];
    const float* bhh_f  = (const float*)d_in[4];
    const float* wih_b  = (const float*)d_in[5];
    const float* whh_b  = (const float*)d_in[6];
    const float* bih_b  = (const float*)d_in[7];
    const float* bhh_b  = (const float*)d_in[8];
    const float* head_w = (const float*)d_in[9];
    const float* head_b = (const float*)d_in[10];
    float* out = (float*)d_out;

    init_out_kernel<<<BTOT / 256, 256>>>(head_b, out);
    lstm_kernel<<<(BTOT / EPB) * 2, BLK>>>(x, wih_f, whh_f, bih_f, bhh_f,
                                           wih_b, whh_b, bih_b, bhh_b,
                                           head_w, out);
}